// round 9
// baseline (speedup 1.0000x reference)
#include <cuda_runtime.h>
#include <cstdint>

// out[p] = (L >= 0) || (missing(p) - L >= 0.5), written as float 0.0/1.0
// L = 7-point Laplacian (6*center - face neighbors, zero padding);
// missing(p) = count of out-of-grid face neighbors (kernel sums to 0, so
// conv(1-m,k) = missing(p) - conv(m,k)).
//
// R8 body (rolling-z x-quad, KZ=6, __stcs) reshaped to 512-thread blocks
// with launch_bounds(512,4): 64 warps/SM (max) to raise in-flight loads.

#define DSZ 192
#define KZ  6
#define ZT  (DSZ / KZ)          // 32 z-tiles
#define QPP (48 * DSZ)          // 9216 x-quads per plane
#define NT  512                 // threads per block
#define QB  (QPP / NT)          // 18 blocks per plane

__global__ __launch_bounds__(NT, 4) void mask_kernel(
    const float* __restrict__ m, float* __restrict__ out)
{
    const int g  = blockIdx.x * NT + threadIdx.x;   // quad id in plane
    const int q  = g % 48;
    const int y  = g / 48;
    const int by = blockIdx.y;
    const int z0 = (by & (ZT - 1)) * KZ;
    const int b  = by >> 5;                          // ZT == 32
    const int x0 = q * 4;

    const size_t plane = (size_t)DSZ * DSZ;
    const float* p = m + (((size_t)b * DSZ + z0) * DSZ + y) * DSZ + x0;
    float* qp = out + (((size_t)b * DSZ + z0) * DSZ + y) * DSZ + x0;

    const float4 zero4 = make_float4(0.f, 0.f, 0.f, 0.f);
    const bool hasYm = (y > 0);
    const bool hasYp = (y < DSZ - 1);
    const bool hasXl = (x0 > 0);
    const bool hasXr = (x0 + 4 < DSZ);
    const int  missY = (int)(!hasYm) + (int)(!hasYp);
    const float missE0 = (float)(missY + (int)(!hasXl));
    const float missE3 = (float)(missY + (int)(!hasXr));
    const float missM  = (float)missY;

    float4 A = (z0 > 0) ? *(const float4*)(p - plane) : zero4;  // z-1
    float4 B = *(const float4*)(p);                              // z

    #pragma unroll
    for (int iz = 0; iz < KZ; ++iz) {
        const int z = z0 + iz;
        float4 C = (z < DSZ - 1) ? *(const float4*)(p + plane) : zero4;  // z+1
        float4 ym = hasYm ? *(const float4*)(p - DSZ) : zero4;
        float4 yp = hasYp ? *(const float4*)(p + DSZ) : zero4;
        float  xl = hasXl ? __ldg(p - 1) : 0.f;
        float  xr = hasXr ? __ldg(p + 4) : 0.f;

        float L0 = 6.f * B.x - (xl  + B.y + ym.x + yp.x + A.x + C.x);
        float L1 = 6.f * B.y - (B.x + B.z + ym.y + yp.y + A.y + C.y);
        float L2 = 6.f * B.z - (B.y + B.w + ym.z + yp.z + A.z + C.z);
        float L3 = 6.f * B.w - (B.z + xr  + ym.w + yp.w + A.w + C.w);

        const float mz = (float)((int)(z == 0) + (int)(z == DSZ - 1));
        const float f0 = missE0 + mz;
        const float fm = missM  + mz;
        const float f3 = missE3 + mz;

        float4 o;
        o.x = ((L0 >= 0.f) || (f0 - L0 >= 0.5f)) ? 1.f : 0.f;
        o.y = ((L1 >= 0.f) || (fm - L1 >= 0.5f)) ? 1.f : 0.f;
        o.z = ((L2 >= 0.f) || (fm - L2 >= 0.5f)) ? 1.f : 0.f;
        o.w = ((L3 >= 0.f) || (f3 - L3 >= 0.5f)) ? 1.f : 0.f;

        __stcs((float4*)qp, o);

        A = B; B = C;
        p += plane; qp += plane;
    }
}

extern "C" void kernel_launch(void* const* d_in, const int* in_sizes, int n_in,
                              void* d_out, int out_size)
{
    const float* m = (const float*)d_in[0];
    float* out = (float*)d_out;

    dim3 block(NT, 1, 1);
    dim3 grid(QB, 2 * ZT, 1);     // 18 quad-chunks x (batch * z-tiles) = 1152
    mask_kernel<<<grid, block>>>(m, out);
}

// round 10
// speedup vs baseline: 1.1014x; 1.1014x over previous
#include <cuda_runtime.h>
#include <cstdint>

// out[p] = (L >= 0) || (missing(p) - L >= 0.5), written as float 0.0/1.0
// L = 7-point Laplacian (6*center - face neighbors, zero padding);
// missing(p) = count of out-of-grid face neighbors (kernel sums to 0, so
// conv(1-m,k) = missing(p) - conv(m,k)).
//
// R8 (rolling-z x-quad, KZ=6, __stcs, 5 CTAs/SM) + shuffle-based x-halo:
// xl/xr come from __shfl of the rolling center row instead of strided
// scalar LDGs (which cost 4 L1 wavefronts each for 4B/lane). Only the two
// warp-edge lanes fall back to a 1-lane predicated load (1 wf each).
// L1 wavefronts per warp-iter: 24 -> 18.

#define DSZ 192
#define KZ  6
#define ZT  (DSZ / KZ)   // 32 z-tiles

__global__ __launch_bounds__(384, 5) void mask_kernel(
    const float* __restrict__ m, float* __restrict__ out)
{
    const int tx = threadIdx.x;                       // 0..47 -> x quad
    const int y  = blockIdx.y * blockDim.y + threadIdx.y;
    const int zb = blockIdx.z;
    const int z0 = (zb & (ZT - 1)) * KZ;
    const int b  = zb / ZT;
    const int x0 = tx * 4;
    const int lane = (threadIdx.y * 48 + tx) & 31;

    const size_t plane = (size_t)DSZ * DSZ;
    const float* p = m + (((size_t)b * DSZ + z0) * DSZ + y) * DSZ + x0;
    float* q = out + (((size_t)b * DSZ + z0) * DSZ + y) * DSZ + x0;

    const float4 zero4 = make_float4(0.f, 0.f, 0.f, 0.f);
    const bool hasYm = (y > 0);
    const bool hasYp = (y < DSZ - 1);
    const bool hasXl = (x0 > 0);
    const bool hasXr = (x0 + 4 < DSZ);
    // lanes that can't get their x-neighbor from a shuffle within this warp
    const bool edgeL = hasXl && (lane == 0);
    const bool edgeR = hasXr && (lane == 31);
    const int  missY = (int)(!hasYm) + (int)(!hasYp);
    const float missE0 = (float)(missY + (int)(!hasXl));
    const float missE3 = (float)(missY + (int)(!hasXr));
    const float missM  = (float)missY;

    float4 A = (z0 > 0) ? *(const float4*)(p - plane) : zero4;  // z-1
    float4 B = *(const float4*)(p);                              // z

    #pragma unroll
    for (int iz = 0; iz < KZ; ++iz) {
        const int z = z0 + iz;
        float4 C = (z < DSZ - 1) ? *(const float4*)(p + plane) : zero4;  // z+1
        float4 ym = hasYm ? *(const float4*)(p - DSZ) : zero4;
        float4 yp = hasYp ? *(const float4*)(p + DSZ) : zero4;

        // x-halo via shuffle of the rolling center row; shfl across the
        // tx=47|0 row wrap is discarded because those are true boundaries.
        float xls = __shfl_up_sync(0xffffffffu, B.w, 1);
        float xrs = __shfl_down_sync(0xffffffffu, B.x, 1);
        float xl = 0.f, xr = 0.f;
        if (hasXl) xl = edgeL ? __ldg(p - 1) : xls;
        if (hasXr) xr = edgeR ? __ldg(p + 4) : xrs;

        float L0 = 6.f * B.x - (xl  + B.y + ym.x + yp.x + A.x + C.x);
        float L1 = 6.f * B.y - (B.x + B.z + ym.y + yp.y + A.y + C.y);
        float L2 = 6.f * B.z - (B.y + B.w + ym.z + yp.z + A.z + C.z);
        float L3 = 6.f * B.w - (B.z + xr  + ym.w + yp.w + A.w + C.w);

        const float mz = (float)((int)(z == 0) + (int)(z == DSZ - 1));
        const float f0 = missE0 + mz;
        const float fm = missM  + mz;
        const float f3 = missE3 + mz;

        float4 o;
        o.x = ((L0 >= 0.f) || (f0 - L0 >= 0.5f)) ? 1.f : 0.f;
        o.y = ((L1 >= 0.f) || (fm - L1 >= 0.5f)) ? 1.f : 0.f;
        o.z = ((L2 >= 0.f) || (fm - L2 >= 0.5f)) ? 1.f : 0.f;
        o.w = ((L3 >= 0.f) || (f3 - L3 >= 0.5f)) ? 1.f : 0.f;

        __stcs((float4*)q, o);

        A = B; B = C;
        p += plane; q += plane;
    }
}

extern "C" void kernel_launch(void* const* d_in, const int* in_sizes, int n_in,
                              void* d_out, int out_size)
{
    const float* m = (const float*)d_in[0];
    float* out = (float*)d_out;

    dim3 block(48, 8, 1);                 // 384 threads: full row x 8 rows
    dim3 grid(1, DSZ / 8, 2 * ZT);        // y-tiles, (batch * z-tiles)
    mask_kernel<<<grid, block>>>(m, out);
}